// round 16
// baseline (speedup 1.0000x reference)
#include <cuda_runtime.h>
#include <cstdint>

#define NN 4096
#define MM 4096
#define NEG_SLOPE 0.01f

#define ROWS_PER_BLOCK 4
#define CONSUMER_WARPS 4
#define THREADS 160                          // 4 consumer warps + 1 producer warp
#define TILE_COLS 512                        // floats per row per stage
#define TILES (MM / TILE_COLS)               // 8
#define STAGES 3
#define STAGE_BYTES (ROWS_PER_BLOCK * TILE_COLS * 4)   // 8192
#define ROW_COPY_BYTES (TILE_COLS * 4)                 // 2048

__device__ __forceinline__ uint32_t smem_u32(const void* p) {
    uint32_t a;
    asm("{ .reg .u64 t; cvta.to.shared.u64 t, %1; cvt.u32.u64 %0, t; }" : "=r"(a) : "l"(p));
    return a;
}
__device__ __forceinline__ void mbar_init(uint32_t mbar, uint32_t count) {
    asm volatile("mbarrier.init.shared::cta.b64 [%0], %1;" :: "r"(mbar), "r"(count) : "memory");
}
__device__ __forceinline__ void mbar_expect_tx(uint32_t mbar, uint32_t bytes) {
    asm volatile("mbarrier.arrive.expect_tx.shared::cta.b64 _, [%0], %1;" :: "r"(mbar), "r"(bytes) : "memory");
}
__device__ __forceinline__ void mbar_arrive(uint32_t mbar) {
    asm volatile("mbarrier.arrive.shared::cta.b64 _, [%0];" :: "r"(mbar) : "memory");
}
__device__ __forceinline__ void bulk_g2s(uint32_t dst, const void* src, uint32_t bytes, uint32_t mbar) {
    asm volatile("cp.async.bulk.shared::cta.global.mbarrier::complete_tx::bytes [%0], [%1], %2, [%3];"
                 :: "r"(dst), "l"(src), "r"(bytes), "r"(mbar) : "memory");
}
// Acquire wait — consumers (generic LDS follows the wait).
__device__ __forceinline__ void mbar_wait(uint32_t mbar, uint32_t parity) {
    asm volatile(
        "{\n\t"
        ".reg .pred P;\n\t"
        "WAIT_%=:\n\t"
        "mbarrier.try_wait.parity.acquire.cta.shared::cta.b64 P, [%0], %1, 0x989680;\n\t"
        "@P bra.uni DONE_%=;\n\t"
        "bra.uni WAIT_%=;\n\t"
        "DONE_%=:\n\t"
        "}"
        :: "r"(mbar), "r"(parity) : "memory");
}
// Relaxed wait — producer only (post-wait accesses are async-proxy TMA).
__device__ __forceinline__ void mbar_wait_relaxed(uint32_t mbar, uint32_t parity) {
    asm volatile(
        "{\n\t"
        ".reg .pred P;\n\t"
        "WAIT_%=:\n\t"
        "mbarrier.try_wait.parity.relaxed.cta.shared::cta.b64 P, [%0], %1, 0x989680;\n\t"
        "@P bra.uni DONE_%=;\n\t"
        "bra.uni WAIT_%=;\n\t"
        "DONE_%=:\n\t"
        "}"
        :: "r"(mbar), "r"(parity) : "memory");
}

// Identity: s=l+u, d=u-l (d>=0):
//   up = 0.5*( sum w*s + sum |w|*d ),  lo = 0.5*( sum w*s - sum |w|*d )
// FINAL kernel: producer/consumer bulk-async pipeline, 3-stage 8 KB ring,
// 24 KB smem -> 7 CTAs/SM, grid 1024 = single all-resident wave.
// Benched 10.72 us x4 (6.3 TB/s effective = path-independent LTS chip cap;
// model closes: 64 MiB / 6.3 TB/s + launch ramp = wall time).
__global__ void __launch_bounds__(THREADS, 7)
abstract_leaky_relu_kernel(const float* __restrict__ lowerBound,
                           const float* __restrict__ upperBound,
                           const float* __restrict__ alpha,
                           const float* __restrict__ W,
                           const float* __restrict__ b,
                           const float* __restrict__ l0,
                           const float* __restrict__ u0,
                           float* __restrict__ out)
{
    __shared__ __align__(128) float smW[STAGES][ROWS_PER_BLOCK][TILE_COLS];  // 24 KB
    __shared__ __align__(8) uint64_t full_bar[STAGES];
    __shared__ __align__(8) uint64_t empty_bar[STAGES];
    __shared__ float s_sc[CONSUMER_WARPS][ROWS_PER_BLOCK];
    __shared__ float s_sd[CONSUMER_WARPS][ROWS_PER_BLOCK];

    const int tid  = threadIdx.x;
    const int warp = tid >> 5;
    const int lane = tid & 31;
    const int row0 = blockIdx.x * ROWS_PER_BLOCK;

    const float* __restrict__ Wb = W + (size_t)row0 * MM;
    const float4* __restrict__ L4 = reinterpret_cast<const float4*>(l0);
    const float4* __restrict__ U4 = reinterpret_cast<const float4*>(u0);

    const uint32_t fb0 = smem_u32(&full_bar[0]);
    const uint32_t eb0 = smem_u32(&empty_bar[0]);

    if (warp == CONSUMER_WARPS) {
        // ---------------- Producer warp ----------------
        if (lane == 0) {
            #pragma unroll
            for (int s = 0; s < STAGES; ++s) {
                mbar_init(fb0 + s * 8, 1);
                mbar_init(eb0 + s * 8, CONSUMER_WARPS);
            }
            asm volatile("fence.proxy.async.shared::cta;" ::: "memory");
        }
        __syncwarp();
        asm volatile("bar.sync 0, %0;" :: "r"(THREADS) : "memory");

        if (lane < ROWS_PER_BLOCK) {
            const float* __restrict__ Wrow = Wb + (size_t)lane * MM;

            // Prologue: fill all 3 stages; lane 0 sets expect_tx, all 4 lanes
            // issue their row copy concurrently.
            #pragma unroll
            for (int s = 0; s < STAGES; ++s) {
                const uint32_t mb = fb0 + s * 8;
                if (lane == 0) mbar_expect_tx(mb, STAGE_BYTES);
                __syncwarp(0xFu);
                bulk_g2s(smem_u32(&smW[s][lane][0]),
                         Wrow + s * TILE_COLS, ROW_COPY_BYTES, mb);
            }
            // Steady-state refills
            #pragma unroll
            for (int ft = STAGES; ft < TILES; ++ft) {
                const int st = ft % STAGES;
                const int ep = ((ft - STAGES) / STAGES) & 1;
                mbar_wait_relaxed(eb0 + st * 8, ep);
                const uint32_t mb = fb0 + st * 8;
                if (lane == 0) mbar_expect_tx(mb, STAGE_BYTES);
                __syncwarp(0xFu);
                bulk_g2s(smem_u32(&smW[st][lane][0]),
                         Wrow + ft * TILE_COLS, ROW_COPY_BYTES, mb);
            }
        }
    } else {
        // ---------------- Consumer warps ----------------
        asm volatile("bar.sync 0, %0;" :: "r"(THREADS) : "memory");

        float sc0 = 0.f, sd0 = 0.f, sc1 = 0.f, sd1 = 0.f;
        float sc2 = 0.f, sd2 = 0.f, sc3 = 0.f, sd3 = 0.f;
        const int f4 = warp * 32 + lane;               // 0..127 within tile

        #pragma unroll
        for (int t = 0; t < TILES; ++t) {
            const int st     = t % STAGES;
            const int parity = (t / STAGES) & 1;

            const float4 lv = L4[t * (TILE_COLS / 4) + f4];
            const float4 uv = U4[t * (TILE_COLS / 4) + f4];

            mbar_wait(fb0 + st * 8, parity);

            const float4 a0 = *reinterpret_cast<const float4*>(&smW[st][0][f4 * 4]);
            const float4 a1 = *reinterpret_cast<const float4*>(&smW[st][1][f4 * 4]);
            const float4 a2 = *reinterpret_cast<const float4*>(&smW[st][2][f4 * 4]);
            const float4 a3 = *reinterpret_cast<const float4*>(&smW[st][3][f4 * 4]);

            float s, d;
            s = lv.x + uv.x; d = uv.x - lv.x;
            sc0 = fmaf(a0.x, s, sc0); sd0 = fmaf(fabsf(a0.x), d, sd0);
            sc1 = fmaf(a1.x, s, sc1); sd1 = fmaf(fabsf(a1.x), d, sd1);
            sc2 = fmaf(a2.x, s, sc2); sd2 = fmaf(fabsf(a2.x), d, sd2);
            sc3 = fmaf(a3.x, s, sc3); sd3 = fmaf(fabsf(a3.x), d, sd3);

            s = lv.y + uv.y; d = uv.y - lv.y;
            sc0 = fmaf(a0.y, s, sc0); sd0 = fmaf(fabsf(a0.y), d, sd0);
            sc1 = fmaf(a1.y, s, sc1); sd1 = fmaf(fabsf(a1.y), d, sd1);
            sc2 = fmaf(a2.y, s, sc2); sd2 = fmaf(fabsf(a2.y), d, sd2);
            sc3 = fmaf(a3.y, s, sc3); sd3 = fmaf(fabsf(a3.y), d, sd3);

            s = lv.z + uv.z; d = uv.z - lv.z;
            sc0 = fmaf(a0.z, s, sc0); sd0 = fmaf(fabsf(a0.z), d, sd0);
            sc1 = fmaf(a1.z, s, sc1); sd1 = fmaf(fabsf(a1.z), d, sd1);
            sc2 = fmaf(a2.z, s, sc2); sd2 = fmaf(fabsf(a2.z), d, sd2);
            sc3 = fmaf(a3.z, s, sc3); sd3 = fmaf(fabsf(a3.z), d, sd3);

            s = lv.w + uv.w; d = uv.w - lv.w;
            sc0 = fmaf(a0.w, s, sc0); sd0 = fmaf(fabsf(a0.w), d, sd0);
            sc1 = fmaf(a1.w, s, sc1); sd1 = fmaf(fabsf(a1.w), d, sd1);
            sc2 = fmaf(a2.w, s, sc2); sd2 = fmaf(fabsf(a2.w), d, sd2);
            sc3 = fmaf(a3.w, s, sc3); sd3 = fmaf(fabsf(a3.w), d, sd3);

            // Only signal stages that will actually be refilled
            if (t < TILES - STAGES) {
                __syncwarp();
                if (lane == 0) mbar_arrive(eb0 + st * 8);
            }
        }

        // Warp reduction
        #pragma unroll
        for (int off = 16; off > 0; off >>= 1) {
            sc0 += __shfl_down_sync(0xFFFFFFFFu, sc0, off);
            sd0 += __shfl_down_sync(0xFFFFFFFFu, sd0, off);
            sc1 += __shfl_down_sync(0xFFFFFFFFu, sc1, off);
            sd1 += __shfl_down_sync(0xFFFFFFFFu, sd1, off);
            sc2 += __shfl_down_sync(0xFFFFFFFFu, sc2, off);
            sd2 += __shfl_down_sync(0xFFFFFFFFu, sd2, off);
            sc3 += __shfl_down_sync(0xFFFFFFFFu, sc3, off);
            sd3 += __shfl_down_sync(0xFFFFFFFFu, sd3, off);
        }
        if (lane == 0) {
            s_sc[warp][0] = sc0; s_sd[warp][0] = sd0;
            s_sc[warp][1] = sc1; s_sd[warp][1] = sd1;
            s_sc[warp][2] = sc2; s_sd[warp][2] = sd2;
            s_sc[warp][3] = sc3; s_sd[warp][3] = sd3;
        }
    }

    __syncthreads();

    if (tid < ROWS_PER_BLOCK) {
        const int r   = tid;
        const int row = row0 + r;

        const float l_i = lowerBound[row];
        const float u_i = upperBound[row];
        const float bi  = b[row];
        const float al  = alpha[row];

        float sc = 0.f, sd = 0.f;
        #pragma unroll
        for (int wI = 0; wI < CONSUMER_WARPS; ++wI) { sc += s_sc[wI][r]; sd += s_sd[wI][r]; }

        const float up = 0.5f * (sc + sd);
        const float lo = 0.5f * (sc - sd);
        const float ns = NEG_SLOPE;

        float lw, uw, ubias = 0.0f;
        if (l_i > 0.0f) {
            lw = 1.0f; uw = 1.0f;
        } else if (l_i < 0.0f && u_i > 0.0f) {
            const float slope = (u_i - ns * l_i) / (u_i - l_i);
            uw = slope;
            ubias = (ns - slope) * l_i;
            lw = fminf(fmaxf(al, ns), 1.0f);
        } else {
            lw = ns; uw = ns;
        }

        out[row]      = lw * (lo + bi);            // lower
        out[NN + row] = uw * (up + bi) + ubias;    // upper
    }
}

extern "C" void kernel_launch(void* const* d_in, const int* in_sizes, int n_in,
                              void* d_out, int out_size)
{
    // metadata order: lowerBound, upperBound, alpha, W, b, l0, u0
    const float* lowerBound = (const float*)d_in[0];
    const float* upperBound = (const float*)d_in[1];
    const float* alpha      = (const float*)d_in[2];
    const float* W          = (const float*)d_in[3];
    const float* b          = (const float*)d_in[4];
    const float* l0         = (const float*)d_in[5];
    const float* u0         = (const float*)d_in[6];
    float* out = (float*)d_out;

    abstract_leaky_relu_kernel<<<NN / ROWS_PER_BLOCK, THREADS>>>(
        lowerBound, upperBound, alpha, W, b, l0, u0, out);
}

// round 17
// speedup vs baseline: 1.0269x; 1.0269x over previous
#include <cuda_runtime.h>
#include <cstdint>

#define NN 4096
#define MM 4096
#define NEG_SLOPE 0.01f

#define ROWS_PER_BLOCK 4
#define CONSUMER_WARPS 4
#define THREADS 160                          // 4 consumer warps + 1 producer warp
#define TILE_COLS 512                        // floats per row per stage
#define TILES (MM / TILE_COLS)               // 8
#define STAGES 3
#define STAGE_BYTES (ROWS_PER_BLOCK * TILE_COLS * 4)   // 8192
#define ROW_COPY_BYTES (TILE_COLS * 4)                 // 2048

__device__ __forceinline__ uint32_t smem_u32(const void* p) {
    uint32_t a;
    asm("{ .reg .u64 t; cvta.to.shared.u64 t, %1; cvt.u32.u64 %0, t; }" : "=r"(a) : "l"(p));
    return a;
}
__device__ __forceinline__ void mbar_init(uint32_t mbar, uint32_t count) {
    asm volatile("mbarrier.init.shared::cta.b64 [%0], %1;" :: "r"(mbar), "r"(count) : "memory");
}
__device__ __forceinline__ void mbar_expect_tx(uint32_t mbar, uint32_t bytes) {
    asm volatile("mbarrier.arrive.expect_tx.shared::cta.b64 _, [%0], %1;" :: "r"(mbar), "r"(bytes) : "memory");
}
__device__ __forceinline__ void mbar_arrive(uint32_t mbar) {
    asm volatile("mbarrier.arrive.shared::cta.b64 _, [%0];" :: "r"(mbar) : "memory");
}
__device__ __forceinline__ void bulk_g2s(uint32_t dst, const void* src, uint32_t bytes, uint32_t mbar) {
    asm volatile("cp.async.bulk.shared::cta.global.mbarrier::complete_tx::bytes [%0], [%1], %2, [%3];"
                 :: "r"(dst), "l"(src), "r"(bytes), "r"(mbar) : "memory");
}
// Acquire wait — consumers (generic LDS follows the wait).
__device__ __forceinline__ void mbar_wait(uint32_t mbar, uint32_t parity) {
    asm volatile(
        "{\n\t"
        ".reg .pred P;\n\t"
        "WAIT_%=:\n\t"
        "mbarrier.try_wait.parity.acquire.cta.shared::cta.b64 P, [%0], %1, 0x989680;\n\t"
        "@P bra.uni DONE_%=;\n\t"
        "bra.uni WAIT_%=;\n\t"
        "DONE_%=:\n\t"
        "}"
        :: "r"(mbar), "r"(parity) : "memory");
}
// Relaxed wait — producer only (post-wait accesses are async-proxy TMA).
__device__ __forceinline__ void mbar_wait_relaxed(uint32_t mbar, uint32_t parity) {
    asm volatile(
        "{\n\t"
        ".reg .pred P;\n\t"
        "WAIT_%=:\n\t"
        "mbarrier.try_wait.parity.relaxed.cta.shared::cta.b64 P, [%0], %1, 0x989680;\n\t"
        "@P bra.uni DONE_%=;\n\t"
        "bra.uni WAIT_%=;\n\t"
        "DONE_%=:\n\t"
        "}"
        :: "r"(mbar), "r"(parity) : "memory");
}

// Identity: s=l+u, d=u-l (d>=0):
//   up = 0.5*( sum w*s + sum |w|*d ),  lo = 0.5*( sum w*s - sum |w|*d )
// FINAL kernel: producer/consumer bulk-async pipeline, 3-stage 8 KB ring,
// 24 KB smem -> 7 CTAs/SM, grid 1024 = single all-resident wave.
// Best measured: 10.72 us (6.3 TB/s effective = path-independent LTS chip
// cap; model closes: 64 MiB / 6.3 TB/s + launch ramp = wall time).
__global__ void __launch_bounds__(THREADS, 7)
abstract_leaky_relu_kernel(const float* __restrict__ lowerBound,
                           const float* __restrict__ upperBound,
                           const float* __restrict__ alpha,
                           const float* __restrict__ W,
                           const float* __restrict__ b,
                           const float* __restrict__ l0,
                           const float* __restrict__ u0,
                           float* __restrict__ out)
{
    __shared__ __align__(128) float smW[STAGES][ROWS_PER_BLOCK][TILE_COLS];  // 24 KB
    __shared__ __align__(8) uint64_t full_bar[STAGES];
    __shared__ __align__(8) uint64_t empty_bar[STAGES];
    __shared__ float s_sc[CONSUMER_WARPS][ROWS_PER_BLOCK];
    __shared__ float s_sd[CONSUMER_WARPS][ROWS_PER_BLOCK];

    const int tid  = threadIdx.x;
    const int warp = tid >> 5;
    const int lane = tid & 31;
    const int row0 = blockIdx.x * ROWS_PER_BLOCK;

    const float* __restrict__ Wb = W + (size_t)row0 * MM;
    const float4* __restrict__ L4 = reinterpret_cast<const float4*>(l0);
    const float4* __restrict__ U4 = reinterpret_cast<const float4*>(u0);

    const uint32_t fb0 = smem_u32(&full_bar[0]);
    const uint32_t eb0 = smem_u32(&empty_bar[0]);

    if (warp == CONSUMER_WARPS) {
        // ---------------- Producer warp ----------------
        if (lane == 0) {
            #pragma unroll
            for (int s = 0; s < STAGES; ++s) {
                mbar_init(fb0 + s * 8, 1);
                mbar_init(eb0 + s * 8, CONSUMER_WARPS);
            }
            asm volatile("fence.proxy.async.shared::cta;" ::: "memory");
        }
        __syncwarp();
        asm volatile("bar.sync 0, %0;" :: "r"(THREADS) : "memory");

        if (lane < ROWS_PER_BLOCK) {
            const float* __restrict__ Wrow = Wb + (size_t)lane * MM;

            // Prologue: fill all 3 stages; lane 0 sets expect_tx, all 4 lanes
            // issue their row copy concurrently.
            #pragma unroll
            for (int s = 0; s < STAGES; ++s) {
                const uint32_t mb = fb0 + s * 8;
                if (lane == 0) mbar_expect_tx(mb, STAGE_BYTES);
                __syncwarp(0xFu);
                bulk_g2s(smem_u32(&smW[s][lane][0]),
                         Wrow + s * TILE_COLS, ROW_COPY_BYTES, mb);
            }
            // Steady-state refills
            #pragma unroll
            for (int ft = STAGES; ft < TILES; ++ft) {
                const int st = ft % STAGES;
                const int ep = ((ft - STAGES) / STAGES) & 1;
                mbar_wait_relaxed(eb0 + st * 8, ep);
                const uint32_t mb = fb0 + st * 8;
                if (lane == 0) mbar_expect_tx(mb, STAGE_BYTES);
                __syncwarp(0xFu);
                bulk_g2s(smem_u32(&smW[st][lane][0]),
                         Wrow + ft * TILE_COLS, ROW_COPY_BYTES, mb);
            }
        }
    } else {
        // ---------------- Consumer warps ----------------
        asm volatile("bar.sync 0, %0;" :: "r"(THREADS) : "memory");

        float sc0 = 0.f, sd0 = 0.f, sc1 = 0.f, sd1 = 0.f;
        float sc2 = 0.f, sd2 = 0.f, sc3 = 0.f, sd3 = 0.f;
        const int f4 = warp * 32 + lane;               // 0..127 within tile

        #pragma unroll
        for (int t = 0; t < TILES; ++t) {
            const int st     = t % STAGES;
            const int parity = (t / STAGES) & 1;

            const float4 lv = L4[t * (TILE_COLS / 4) + f4];
            const float4 uv = U4[t * (TILE_COLS / 4) + f4];

            mbar_wait(fb0 + st * 8, parity);

            const float4 a0 = *reinterpret_cast<const float4*>(&smW[st][0][f4 * 4]);
            const float4 a1 = *reinterpret_cast<const float4*>(&smW[st][1][f4 * 4]);
            const float4 a2 = *reinterpret_cast<const float4*>(&smW[st][2][f4 * 4]);
            const float4 a3 = *reinterpret_cast<const float4*>(&smW[st][3][f4 * 4]);

            float s, d;
            s = lv.x + uv.x; d = uv.x - lv.x;
            sc0 = fmaf(a0.x, s, sc0); sd0 = fmaf(fabsf(a0.x), d, sd0);
            sc1 = fmaf(a1.x, s, sc1); sd1 = fmaf(fabsf(a1.x), d, sd1);
            sc2 = fmaf(a2.x, s, sc2); sd2 = fmaf(fabsf(a2.x), d, sd2);
            sc3 = fmaf(a3.x, s, sc3); sd3 = fmaf(fabsf(a3.x), d, sd3);

            s = lv.y + uv.y; d = uv.y - lv.y;
            sc0 = fmaf(a0.y, s, sc0); sd0 = fmaf(fabsf(a0.y), d, sd0);
            sc1 = fmaf(a1.y, s, sc1); sd1 = fmaf(fabsf(a1.y), d, sd1);
            sc2 = fmaf(a2.y, s, sc2); sd2 = fmaf(fabsf(a2.y), d, sd2);
            sc3 = fmaf(a3.y, s, sc3); sd3 = fmaf(fabsf(a3.y), d, sd3);

            s = lv.z + uv.z; d = uv.z - lv.z;
            sc0 = fmaf(a0.z, s, sc0); sd0 = fmaf(fabsf(a0.z), d, sd0);
            sc1 = fmaf(a1.z, s, sc1); sd1 = fmaf(fabsf(a1.z), d, sd1);
            sc2 = fmaf(a2.z, s, sc2); sd2 = fmaf(fabsf(a2.z), d, sd2);
            sc3 = fmaf(a3.z, s, sc3); sd3 = fmaf(fabsf(a3.z), d, sd3);

            s = lv.w + uv.w; d = uv.w - lv.w;
            sc0 = fmaf(a0.w, s, sc0); sd0 = fmaf(fabsf(a0.w), d, sd0);
            sc1 = fmaf(a1.w, s, sc1); sd1 = fmaf(fabsf(a1.w), d, sd1);
            sc2 = fmaf(a2.w, s, sc2); sd2 = fmaf(fabsf(a2.w), d, sd2);
            sc3 = fmaf(a3.w, s, sc3); sd3 = fmaf(fabsf(a3.w), d, sd3);

            // Only signal stages that will actually be refilled
            if (t < TILES - STAGES) {
                __syncwarp();
                if (lane == 0) mbar_arrive(eb0 + st * 8);
            }
        }

        // Warp reduction
        #pragma unroll
        for (int off = 16; off > 0; off >>= 1) {
            sc0 += __shfl_down_sync(0xFFFFFFFFu, sc0, off);
            sd0 += __shfl_down_sync(0xFFFFFFFFu, sd0, off);
            sc1 += __shfl_down_sync(0xFFFFFFFFu, sc1, off);
            sd1 += __shfl_down_sync(0xFFFFFFFFu, sd1, off);
            sc2 += __shfl_down_sync(0xFFFFFFFFu, sc2, off);
            sd2 += __shfl_down_sync(0xFFFFFFFFu, sd2, off);
            sc3 += __shfl_down_sync(0xFFFFFFFFu, sc3, off);
            sd3 += __shfl_down_sync(0xFFFFFFFFu, sd3, off);
        }
        if (lane == 0) {
            s_sc[warp][0] = sc0; s_sd[warp][0] = sd0;
            s_sc[warp][1] = sc1; s_sd[warp][1] = sd1;
            s_sc[warp][2] = sc2; s_sd[warp][2] = sd2;
            s_sc[warp][3] = sc3; s_sd[warp][3] = sd3;
        }
    }

    __syncthreads();

    if (tid < ROWS_PER_BLOCK) {
        const int r   = tid;
        const int row = row0 + r;

        const float l_i = lowerBound[row];
        const float u_i = upperBound[row];
        const float bi  = b[row];
        const float al  = alpha[row];

        float sc = 0.f, sd = 0.f;
        #pragma unroll
        for (int wI = 0; wI < CONSUMER_WARPS; ++wI) { sc += s_sc[wI][r]; sd += s_sd[wI][r]; }

        const float up = 0.5f * (sc + sd);
        const float lo = 0.5f * (sc - sd);
        const float ns = NEG_SLOPE;

        float lw, uw, ubias = 0.0f;
        if (l_i > 0.0f) {
            lw = 1.0f; uw = 1.0f;
        } else if (l_i < 0.0f && u_i > 0.0f) {
            const float slope = (u_i - ns * l_i) / (u_i - l_i);
            uw = slope;
            ubias = (ns - slope) * l_i;
            lw = fminf(fmaxf(al, ns), 1.0f);
        } else {
            lw = ns; uw = ns;
        }

        out[row]      = lw * (lo + bi);            // lower
        out[NN + row] = uw * (up + bi) + ubias;    // upper
    }
}

extern "C" void kernel_launch(void* const* d_in, const int* in_sizes, int n_in,
                              void* d_out, int out_size)
{
    // metadata order: lowerBound, upperBound, alpha, W, b, l0, u0
    const float* lowerBound = (const float*)d_in[0];
    const float* upperBound = (const float*)d_in[1];
    const float* alpha      = (const float*)d_in[2];
    const float* W          = (const float*)d_in[3];
    const float* b          = (const float*)d_in[4];
    const float* l0         = (const float*)d_in[5];
    const float* u0         = (const float*)d_in[6];
    float* out = (float*)d_out;

    abstract_leaky_relu_kernel<<<NN / ROWS_PER_BLOCK, THREADS>>>(
        lowerBound, upperBound, alpha, W, b, l0, u0, out);
}